// round 10
// baseline (speedup 1.0000x reference)
#include <cuda_runtime.h>
#include <cstdint>
#include <cstdlib>

// Eager module loading: __device__ globals allocated at context init.
__attribute__((constructor)) static void _force_eager_loading() {
    setenv("CUDA_MODULE_LOADING", "EAGER", 1);
}

#define NN     2048
#define TT     512
#define ROWS_C (NN*TT)        /* 1048576 */
#define ER_C   (NN*(TT-1))    /* 1046528 */
#define BN_EPS 1e-5

// K1: 192 threads = 6 warps x 32 rows
#define RPB1   192
#define NB1    5462           /* ceil(ROWS_C/192) */
// K2: 256 threads = 8 warps x 32 rows
#define RPB2   256
#define NB2    (ROWS_C/RPB2)  /* 4096 */

typedef unsigned long long u64;

// K1 smem float offsets: weights 0..3264, U 3264..10320, V 10320..17376,
//                        A/x 17376..24288, WS 24288..25440
#define K1_U    3264
#define K1_V    10320
#define K1_A    17376
#define K1_WS   24288
#define K1_TOT  25440         /* 101760 B */
// K2 smem float offsets (node weights + scale/bias + A stage + WS)
#define N_A    3360
#define N_WS   12576
#define N_TOT  13088          /* 52352 B */

// ---- device scratch ----
__device__ float g_cf[(size_t)ER_C * 32];   // fwd pre-BN cache (134 MB)
__device__ float g_cb[(size_t)ER_C * 32];   // bwd pre-BN cache (134 MB)
__device__ float g_epart[3][2][32][NB1];
__device__ float g_npart[2][32][NB2];
__device__ float g_escale[3][32], g_ebias[3][32];
__device__ float g_nscale[32],    g_nbias[32];

// ---- packed f32x2 helpers ----
__device__ __forceinline__ u64 pk(float x, float y) {
    u64 d; asm("mov.b64 %0, {%1, %2};" : "=l"(d) : "f"(x), "f"(y)); return d;
}
__device__ __forceinline__ void upk(u64 v, float& lo, float& hi) {
    asm("mov.b64 {%0, %1}, %2;" : "=f"(lo), "=f"(hi) : "l"(v));
}
__device__ __forceinline__ u64 fma2(u64 a, u64 b, u64 c) {
    u64 d; asm("fma.rn.f32x2 %0, %1, %2, %3;" : "=l"(d) : "l"(a), "l"(b), "l"(c)); return d;
}
__device__ __forceinline__ float lrelu(float x) { return fmaxf(x, 0.01f * x); }

// accumulate 4 row-activations against one weight row into the 4x8 tile
__device__ __forceinline__ void accum_row(const u64* __restrict__ wrow, int c_g,
                                          float a0, float a1, float a2, float a3, u64* h) {
    ulonglong2 wA = *reinterpret_cast<const ulonglong2*>(wrow + c_g * 4);
    ulonglong2 wB = *reinterpret_cast<const ulonglong2*>(wrow + c_g * 4 + 2);
    u64 x;
    x = pk(a0, a0); h[0] = fma2(x, wA.x, h[0]); h[1] = fma2(x, wA.y, h[1]);
                    h[2] = fma2(x, wB.x, h[2]); h[3] = fma2(x, wB.y, h[3]);
    x = pk(a1, a1); h[4] = fma2(x, wA.x, h[4]); h[5] = fma2(x, wA.y, h[5]);
                    h[6] = fma2(x, wB.x, h[6]); h[7] = fma2(x, wB.y, h[7]);
    x = pk(a2, a2); h[8] = fma2(x, wA.x, h[8]); h[9] = fma2(x, wA.y, h[9]);
                    h[10] = fma2(x, wB.x, h[10]); h[11] = fma2(x, wB.y, h[11]);
    x = pk(a3, a3); h[12] = fma2(x, wA.x, h[12]); h[13] = fma2(x, wA.y, h[13]);
                    h[14] = fma2(x, wB.x, h[14]); h[15] = fma2(x, wB.y, h[15]);
}

// 32x32 GEMM layer: A staged [k][row] stride 36, lane tile 4 rows x 8 cols
__device__ __forceinline__ void gemm32(const float* __restrict__ As,
                                       const u64* __restrict__ W, const u64* __restrict__ B,
                                       int r_g, int c_g, u64* h) {
#pragma unroll
    for (int cp = 0; cp < 4; cp++) {
        u64 v = B[c_g * 4 + cp];
        h[cp] = v; h[4 + cp] = v; h[8 + cp] = v; h[12 + cp] = v;
    }
#pragma unroll 4
    for (int k = 0; k < 32; k++) {
        float4 t = *reinterpret_cast<const float4*>(As + k * 36 + 4 * r_g);
        accum_row(W + k * 16, c_g, t.x, t.y, t.z, t.w, h);
    }
}

// 16-k gemm, no bias, A = staged x [k][row] stride 196 (pre-offset by warp rows)
__device__ __forceinline__ void gemm16_x(const float* __restrict__ xs,
                                         const u64* __restrict__ W,
                                         int r_g, int c_g, u64* h) {
#pragma unroll
    for (int i = 0; i < 16; i++) h[i] = 0ull;
#pragma unroll 4
    for (int k = 0; k < 16; k++) {
        float4 t = *reinterpret_cast<const float4*>(xs + k * 196 + 4 * r_g);
        accum_row(W + k * 16, c_g, t.x, t.y, t.z, t.w, h);
    }
}

__device__ __forceinline__ void unpack_tile(const u64* h, float o[4][8], bool relu) {
#pragma unroll
    for (int r = 0; r < 4; r++)
#pragma unroll
        for (int cp = 0; cp < 4; cp++) {
            float lo, hi; upk(h[r * 4 + cp], lo, hi);
            o[r][2 * cp]     = relu ? lrelu(lo) : lo;
            o[r][2 * cp + 1] = relu ? lrelu(hi) : hi;
        }
}

// store lane tile transposed into A buffer (A[col][row], stride 36)
__device__ __forceinline__ void stage_tile(float* As, int r_g, int c_g, const float o[4][8]) {
    __syncwarp();
#pragma unroll
    for (int cc = 0; cc < 8; cc++) {
        *reinterpret_cast<float4*>(As + (8 * c_g + cc) * 36 + 4 * r_g) =
            make_float4(o[0][cc], o[1][cc], o[2][cc], o[3][cc]);
    }
    __syncwarp();
}

// store U/V tile row-major [row][ch] stride 36
__device__ __forceinline__ void store_uv(float* Ub, int wbase, int r_g, int c_g,
                                         const float o[4][8]) {
#pragma unroll
    for (int rr = 0; rr < 4; rr++) {
        float* p = Ub + (wbase + 4 * r_g + rr) * 36 + 8 * c_g;
        *reinterpret_cast<float4*>(p)     = make_float4(o[rr][0], o[rr][1], o[rr][2], o[rr][3]);
        *reinterpret_cast<float4*>(p + 4) = make_float4(o[rr][4], o[rr][5], o[rr][6], o[rr][7]);
    }
}

// build L1 activation tile from U,V smem + bias; du/dv = row shift for U/V
__device__ __forceinline__ void build_act(const float* __restrict__ Ub,
                                          const float* __restrict__ Vb,
                                          const float* __restrict__ bias,
                                          int du, int dv, int wbase,
                                          int r_g, int c_g, float o[4][8]) {
    float b[8];
#pragma unroll
    for (int j = 0; j < 8; j++) b[j] = bias[8 * c_g + j];
#pragma unroll
    for (int rr = 0; rr < 4; rr++) {
        int srow = wbase + 4 * r_g + rr;
        const float4* up = reinterpret_cast<const float4*>(Ub + (srow + du) * 36 + 8 * c_g);
        const float4* vp = reinterpret_cast<const float4*>(Vb + (srow + dv) * 36 + 8 * c_g);
        float4 ua = up[0], ub2 = up[1], va = vp[0], vb2 = vp[1];
        o[rr][0] = lrelu(ua.x + va.x + b[0]);
        o[rr][1] = lrelu(ua.y + va.y + b[1]);
        o[rr][2] = lrelu(ua.z + va.z + b[2]);
        o[rr][3] = lrelu(ua.w + va.w + b[3]);
        o[rr][4] = lrelu(ub2.x + vb2.x + b[4]);
        o[rr][5] = lrelu(ub2.y + vb2.y + b[5]);
        o[rr][6] = lrelu(ub2.z + vb2.z + b[6]);
        o[rr][7] = lrelu(ub2.w + vb2.w + b[7]);
    }
}

// L2+L3 (input o already staged in As)
__device__ __forceinline__ void tail23(float* As,
                                       const u64* W2, const u64* B2,
                                       const u64* W3, const u64* B3,
                                       int r_g, int c_g, u64* h, float o[4][8]) {
    gemm32(As, W2, B2, r_g, c_g, h);
    unpack_tile(h, o, true);
    stage_tile(As, r_g, c_g, o);
    gemm32(As, W3, B3, r_g, c_g, h);
    unpack_tile(h, o, false);
}

// per-warp masked per-channel sum/sumsq -> ws[warp][c]
__device__ __forceinline__ void warp_stats(const float o[4][8], const float m[4],
                                           int lane, int c_g, float* wsS, float* wsQ) {
    float s[8], q[8];
#pragma unroll
    for (int cc = 0; cc < 8; cc++) { s[cc] = 0.f; q[cc] = 0.f; }
#pragma unroll
    for (int r = 0; r < 4; r++)
#pragma unroll
        for (int cc = 0; cc < 8; cc++) {
            float v = o[r][cc] * m[r];
            s[cc] += v; q[cc] += v * v;
        }
#pragma unroll
    for (int msk = 4; msk <= 16; msk <<= 1)
#pragma unroll
        for (int cc = 0; cc < 8; cc++) {
            s[cc] += __shfl_xor_sync(0xffffffffu, s[cc], msk);
            q[cc] += __shfl_xor_sync(0xffffffffu, q[cc], msk);
        }
    if (lane < 4) {
#pragma unroll
        for (int cc = 0; cc < 8; cc++) { wsS[8 * c_g + cc] = s[cc]; wsQ[8 * c_g + cc] = q[cc]; }
    }
}

// ---------------- K1: U/V shared L1; 3 edge chains; caches + stats ----------------
__global__ __launch_bounds__(192, 2) void k_edge(
    const float* __restrict__ x, float* __restrict__ dout,
    const float* __restrict__ eW1, const float* __restrict__ eb1,
    const float* __restrict__ eW2, const float* __restrict__ eb2,
    const float* __restrict__ eW3, const float* __restrict__ eb3)
{
    extern __shared__ float sm[];
    const int tid = threadIdx.x, bid = blockIdx.x;
    const int r0b = bid * RPB1;

    // weights + bias variants
    for (int i = tid; i < 3264; i += 192) {
        float v;
        if      (i < 1056) v = eW1[i];
        else if (i < 1088) v = eb1[i - 1056];                              // b10
        else if (i < 1120) v = eb1[i - 1088] + eW1[1024 + (i - 1088)];     // b1p = b + w_dir
        else if (i < 1152) v = eb1[i - 1120] - eW1[1024 + (i - 1120)];     // b1m = b - w_dir
        else if (i < 2176) v = eW2[i - 1152];
        else if (i < 2208) v = eb2[i - 2176];
        else if (i < 3232) v = eW3[i - 2208];
        else               v = eb3[i - 3232];
        sm[i] = v;
    }
    // stage x rows r0b..r0b+192 transposed [k][srow] stride 196 (overlaps A region)
    float* xs = sm + K1_A;
    for (int idx = tid; idx < 193 * 16; idx += 192) {
        int srow = idx >> 4, k = idx & 15;
        int row = r0b + srow; if (row > ROWS_C - 1) row = ROWS_C - 1;
        xs[k * 196 + srow] = x[(size_t)row * 16 + k];
    }
    __syncthreads();

    const u64* W1 = (const u64*)sm;
    const float* b10 = sm + 1056;
    const float* b1p = sm + 1088;
    const float* b1m = sm + 1120;
    const u64* W2 = (const u64*)(sm + 1152);
    const u64* B2 = (const u64*)(sm + 2176);
    const u64* W3 = (const u64*)(sm + 2208);
    const u64* B3 = (const u64*)(sm + 3232);
    float* Ub = sm + K1_U;
    float* Vb = sm + K1_V;

    int lane = tid & 31, warp = tid >> 5;
    int r_g = lane >> 2, c_g = lane & 3;
    int wbase = warp * 32;
    float* Asw = sm + K1_A + warp * 1152;

    u64 h[16];
    float o[4][8];

    // U = W1_p x, V = W1_q x for this warp's 32 rows
    gemm16_x(xs + wbase, W1, r_g, c_g, h);
    unpack_tile(h, o, false);
    store_uv(Ub, wbase, r_g, c_g, o);
    gemm16_x(xs + wbase, W1 + 16 * 16, r_g, c_g, h);
    unpack_tile(h, o, false);
    store_uv(Vb, wbase, r_g, c_g, o);

    // boundary row 192: 32 lanes of warp 0, one channel each
    if (warp == 0) {
        float u = 0.f, v = 0.f;
#pragma unroll
        for (int k = 0; k < 16; k++) {
            float xv = xs[k * 196 + 192];
            u += xv * sm[k * 32 + lane];
            v += xv * sm[(16 + k) * 32 + lane];
        }
        Ub[192 * 36 + lane] = u;
        Vb[192 * 36 + lane] = v;
    }
    __syncthreads();   // U/V visible cross-warp; xs free for reuse as As

    // validity masks
    int rb = r0b + wbase + 4 * r_g;
    float m_in[4], m_e[4];
#pragma unroll
    for (int rr = 0; rr < 4; rr++) {
        int r = rb + rr;
        bool vr = r < ROWS_C;
        m_in[rr] = vr ? 1.f : 0.f;
        m_e[rr]  = (vr && ((r & 511) != 511)) ? 1.f : 0.f;
    }

    // ---- inplace chain: U_t + V_t + b
    build_act(Ub, Vb, b10, 0, 0, wbase, r_g, c_g, o);
    stage_tile(Asw, r_g, c_g, o);
    tail23(Asw, W2, B2, W3, B3, r_g, c_g, h, o);
#pragma unroll
    for (int rr = 0; rr < 4; rr++) {
        int r = rb + rr;
        if (r < ROWS_C) {
            float4* p = reinterpret_cast<float4*>(dout) + (size_t)r * 8 + c_g * 2;
            p[0] = make_float4(o[rr][0], o[rr][1], o[rr][2], o[rr][3]);
            p[1] = make_float4(o[rr][4], o[rr][5], o[rr][6], o[rr][7]);
        }
    }
    warp_stats(o, m_in, lane, c_g, sm + K1_WS + (0 * 6 + warp) * 32, sm + K1_WS + (1 * 6 + warp) * 32);

    // ---- fwd chain: U_{t+1} + V_t + (b + w_dir)
    build_act(Ub, Vb, b1p, 1, 0, wbase, r_g, c_g, o);
    stage_tile(Asw, r_g, c_g, o);
    tail23(Asw, W2, B2, W3, B3, r_g, c_g, h, o);
#pragma unroll
    for (int rr = 0; rr < 4; rr++) {
        int r = rb + rr;
        if (r < ROWS_C && (r & 511) != 511) {
            int e = r - (r >> 9);
            float4* p = reinterpret_cast<float4*>(g_cf + (size_t)e * 32 + 8 * c_g);
            p[0] = make_float4(o[rr][0], o[rr][1], o[rr][2], o[rr][3]);
            p[1] = make_float4(o[rr][4], o[rr][5], o[rr][6], o[rr][7]);
        }
    }
    warp_stats(o, m_e, lane, c_g, sm + K1_WS + (2 * 6 + warp) * 32, sm + K1_WS + (3 * 6 + warp) * 32);

    // ---- bwd chain: U_t + V_{t+1} + (b - w_dir)
    build_act(Ub, Vb, b1m, 0, 1, wbase, r_g, c_g, o);
    stage_tile(Asw, r_g, c_g, o);
    tail23(Asw, W2, B2, W3, B3, r_g, c_g, h, o);
#pragma unroll
    for (int rr = 0; rr < 4; rr++) {
        int r = rb + rr;
        if (r < ROWS_C && (r & 511) != 511) {
            int e = r - (r >> 9);
            float4* p = reinterpret_cast<float4*>(g_cb + (size_t)e * 32 + 8 * c_g);
            p[0] = make_float4(o[rr][0], o[rr][1], o[rr][2], o[rr][3]);
            p[1] = make_float4(o[rr][4], o[rr][5], o[rr][6], o[rr][7]);
        }
    }
    warp_stats(o, m_e, lane, c_g, sm + K1_WS + (4 * 6 + warp) * 32, sm + K1_WS + (5 * 6 + warp) * 32);

    __syncthreads();
    {
        int chain = tid / 64, st = (tid >> 5) & 1, c = tid & 31;  // 192 threads = 3x2x32
        float a = 0.f;
#pragma unroll
        for (int w = 0; w < 6; w++) a += sm[K1_WS + ((chain * 2 + st) * 6 + w) * 32 + c];
        g_epart[chain][st][c][bid] = a;
    }
}

// ---------------- stats finalize ----------------
__global__ void k_fin_edge(const float* __restrict__ gamma, const float* __restrict__ beta) {
    int arr = blockIdx.x >> 5, c = blockIdx.x & 31;
    int tid = threadIdx.x;
    __shared__ double ss[256], sq[256];
    double sa = 0.0, sb = 0.0, qa = 0.0, qb = 0.0;
    const float* ps = &g_epart[arr][0][c][0];
    const float* pz = &g_epart[arr][1][c][0];
    for (int i = tid; i < NB1; i += 512) {
        sa += ps[i]; qa += pz[i];
        if (i + 256 < NB1) { sb += ps[i + 256]; qb += pz[i + 256]; }
    }
    ss[tid] = sa + sb; sq[tid] = qa + qb;
    __syncthreads();
    for (int o = 128; o > 0; o >>= 1) {
        if (tid < o) { ss[tid] += ss[tid + o]; sq[tid] += sq[tid + o]; }
        __syncthreads();
    }
    if (tid == 0) {
        double M   = (arr == 0) ? (double)ROWS_C : (double)ER_C;
        double mu  = ss[0] / M;
        double var = sq[0] / M - mu * mu;
        double inv = 1.0 / sqrt(var + BN_EPS);
        g_escale[arr][c] = (float)((double)gamma[c] * inv);
        g_ebias [arr][c] = (float)((double)beta[c] - mu * (double)gamma[c] * inv);
    }
}

__global__ void k_fin_node(const float* __restrict__ gamma, const float* __restrict__ beta) {
    int c = blockIdx.x;
    int tid = threadIdx.x;
    __shared__ double ss[256], sq[256];
    double sa = 0.0, sb = 0.0, qa = 0.0, qb = 0.0;
    const float* ps = &g_npart[0][c][0];
    const float* pz = &g_npart[1][c][0];
    for (int i = tid; i < NB2; i += 512) {
        sa += ps[i]; qa += pz[i];
        if (i + 256 < NB2) { sb += ps[i + 256]; qb += pz[i + 256]; }
    }
    ss[tid] = sa + sb; sq[tid] = qa + qb;
    __syncthreads();
    for (int o = 128; o > 0; o >>= 1) {
        if (tid < o) { ss[tid] += ss[tid + o]; sq[tid] += sq[tid + o]; }
        __syncthreads();
    }
    if (tid == 0) {
        double M   = (double)ROWS_C;
        double mu  = ss[0] / M;
        double var = sq[0] / M - mu * mu;
        double inv = 1.0 / sqrt(var + BN_EPS);
        g_nscale[c] = (float)((double)gamma[c] * inv);
        g_nbias [c] = (float)((double)beta[c] - mu * (double)gamma[c] * inv);
    }
}

// ---------------- K2: affine-aggregate cached edges + node MLP + node stats ----------------
__global__ __launch_bounds__(256, 2) void k_node(
    float* __restrict__ dout,
    const float* __restrict__ nW1, const float* __restrict__ nb1,
    const float* __restrict__ nW2, const float* __restrict__ nb2,
    const float* __restrict__ nW3, const float* __restrict__ nb3)
{
    extern __shared__ float sm[];
    const int tid = threadIdx.x, bid = blockIdx.x;
    for (int i = tid; i < 3360; i += 256) {
        float v;
        if      (i < 1024) v = nW1[i];
        else if (i < 1056) v = nb1[i - 1024];
        else if (i < 2080) v = nW2[i - 1056];
        else if (i < 2112) v = nb2[i - 2080];
        else if (i < 3136) v = nW3[i - 2112];
        else if (i < 3168) v = nb3[i - 3136];
        else {
            int k = i - 3168;
            int arr = k / 64, sb = (k >> 5) & 1, c = k & 31;
            v = sb ? g_ebias[arr][c] : g_escale[arr][c];
        }
        sm[i] = v;
    }
    __syncthreads();

    const u64* nW1s = (const u64*)(sm);
    const u64* nB1s = (const u64*)(sm + 1024);
    const u64* nW2s = (const u64*)(sm + 1056);
    const u64* nB2s = (const u64*)(sm + 2080);
    const u64* nW3s = (const u64*)(sm + 2112);
    const u64* nB3s = (const u64*)(sm + 3136);
    const float* s0 = sm + 3168; const float* b0 = sm + 3200;
    const float* s1 = sm + 3232; const float* b1 = sm + 3264;
    const float* s2 = sm + 3296; const float* b2 = sm + 3328;

    int lane = tid & 31, warp = tid >> 5;
    int r_g = lane >> 2, c_g = lane & 3;
    float* Asw = sm + N_A + warp * 1152;
    int r0 = bid * 256 + warp * 32;
    int n0 = bid >> 1;
    int c0 = 8 * c_g;

    float agg[4][8];
    float o[4][8];

#pragma unroll
    for (int rr = 0; rr < 4; rr++) {
        int r = r0 + 4 * r_g + rr;
        int t = r & 511;
        float mf = (t != 0)   ? 1.f : 0.f;
        float mb = (t != 511) ? 1.f : 0.f;

        const float4* ip = reinterpret_cast<const float4*>(dout) + (size_t)r * 8 + c_g * 2;
        float4 va = ip[0], vb = ip[1];
        agg[rr][0] = s0[c0+0]*va.x + b0[c0+0]; agg[rr][1] = s0[c0+1]*va.y + b0[c0+1];
        agg[rr][2] = s0[c0+2]*va.z + b0[c0+2]; agg[rr][3] = s0[c0+3]*va.w + b0[c0+3];
        agg[rr][4] = s0[c0+4]*vb.x + b0[c0+4]; agg[rr][5] = s0[c0+5]*vb.y + b0[c0+5];
        agg[rr][6] = s0[c0+6]*vb.z + b0[c0+6]; agg[rr][7] = s0[c0+7]*vb.w + b0[c0+7];

        {
            long e = (long)r - n0 - 1; if (e < 0) e = 0;
            const float4* fp = reinterpret_cast<const float4*>(g_cf + (size_t)e * 32 + c0);
            float4 fa = fp[0], fb = fp[1];
            agg[rr][0] += mf * (s1[c0+0]*fa.x + b1[c0+0]);
            agg[rr][1] += mf * (s1[c0+1]*fa.y + b1[c0+1]);
            agg[rr][2] += mf * (s1[c0+2]*fa.z + b1[c0+2]);
            agg[rr][3] += mf * (s1[c0+3]*fa.w + b1[c0+3]);
            agg[rr][4] += mf * (s1[c0+4]*fb.x + b1[c0+4]);
            agg[rr][5] += mf * (s1[c0+5]*fb.y + b1[c0+5]);
            agg[rr][6] += mf * (s1[c0+6]*fb.z + b1[c0+6]);
            agg[rr][7] += mf * (s1[c0+7]*fb.w + b1[c0+7]);
        }
        {
            long e = (long)r - n0; if (e > ER_C - 1) e = ER_C - 1;
            const float4* bp = reinterpret_cast<const float4*>(g_cb + (size_t)e * 32 + c0);
            float4 ba = bp[0], bb = bp[1];
            agg[rr][0] += mb * (s2[c0+0]*ba.x + b2[c0+0]);
            agg[rr][1] += mb * (s2[c0+1]*ba.y + b2[c0+1]);
            agg[rr][2] += mb * (s2[c0+2]*ba.z + b2[c0+2]);
            agg[rr][3] += mb * (s2[c0+3]*ba.w + b2[c0+3]);
            agg[rr][4] += mb * (s2[c0+4]*bb.x + b2[c0+4]);
            agg[rr][5] += mb * (s2[c0+5]*bb.y + b2[c0+5]);
            agg[rr][6] += mb * (s2[c0+6]*bb.z + b2[c0+6]);
            agg[rr][7] += mb * (s2[c0+7]*bb.w + b2[c0+7]);
        }
    }

    u64 h[16];
    stage_tile(Asw, r_g, c_g, agg);
    gemm32(Asw, nW1s, nB1s, r_g, c_g, h);
    unpack_tile(h, o, true);
    stage_tile(Asw, r_g, c_g, o);
    tail23(Asw, nW2s, nB2s, nW3s, nB3s, r_g, c_g, h, o);
#pragma unroll
    for (int rr = 0; rr < 4; rr++) {
        float4* p = reinterpret_cast<float4*>(dout) + (size_t)(r0 + 4 * r_g + rr) * 8 + c_g * 2;
        p[0] = make_float4(o[rr][0], o[rr][1], o[rr][2], o[rr][3]);
        p[1] = make_float4(o[rr][4], o[rr][5], o[rr][6], o[rr][7]);
    }
    {
        float mall[4] = {1.f, 1.f, 1.f, 1.f};
        warp_stats(o, mall, lane, c_g, sm + N_WS + (0 * 8 + warp) * 32, sm + N_WS + (1 * 8 + warp) * 32);
    }

    __syncthreads();
    if (tid < 64) {
        int st = tid >> 5, c = tid & 31;
        float a = 0.f;
#pragma unroll
        for (int w = 0; w < 8; w++) a += sm[N_WS + (st * 8 + w) * 32 + c];
        g_npart[st][c][bid] = a;
    }
}

// ---------------- K3: normalize in place ----------------
__global__ __launch_bounds__(256) void k_final(float* __restrict__ dout) {
    __shared__ float sc[32], bi[32];
    int tid = threadIdx.x;
    if (tid < 32) { sc[tid] = g_nscale[tid]; bi[tid] = g_nbias[tid]; }
    __syncthreads();
    int lane = tid & 31;
    int s = lane & 3;
    int r = (blockIdx.x * 256 + tid) >> 2;
    int c0 = s * 8;
    float4* D4 = reinterpret_cast<float4*>(dout);
    float4 va = D4[(size_t)r * 8 + s * 2];
    float4 vb = D4[(size_t)r * 8 + s * 2 + 1];
    va.x = va.x * sc[c0 + 0] + bi[c0 + 0]; va.y = va.y * sc[c0 + 1] + bi[c0 + 1];
    va.z = va.z * sc[c0 + 2] + bi[c0 + 2]; va.w = va.w * sc[c0 + 3] + bi[c0 + 3];
    vb.x = vb.x * sc[c0 + 4] + bi[c0 + 4]; vb.y = vb.y * sc[c0 + 5] + bi[c0 + 5];
    vb.z = vb.z * sc[c0 + 6] + bi[c0 + 6]; vb.w = vb.w * sc[c0 + 7] + bi[c0 + 7];
    D4[(size_t)r * 8 + s * 2]     = va;
    D4[(size_t)r * 8 + s * 2 + 1] = vb;
}

// ---------------- launch ----------------
extern "C" void kernel_launch(void* const* d_in, const int* in_sizes, int n_in,
                              void* d_out, int out_size)
{
    const float* x    = (const float*)d_in[0];
    const float* eW1  = (const float*)d_in[1];
    const float* eb1  = (const float*)d_in[2];
    const float* eW2  = (const float*)d_in[3];
    const float* eb2  = (const float*)d_in[4];
    const float* eW3  = (const float*)d_in[5];
    const float* eb3  = (const float*)d_in[6];
    const float* eg   = (const float*)d_in[7];
    const float* ebt  = (const float*)d_in[8];
    const float* nW1  = (const float*)d_in[9];
    const float* nb1  = (const float*)d_in[10];
    const float* nW2  = (const float*)d_in[11];
    const float* nb2  = (const float*)d_in[12];
    const float* nW3  = (const float*)d_in[13];
    const float* nb3  = (const float*)d_in[14];
    const float* ng   = (const float*)d_in[15];
    const float* nbt  = (const float*)d_in[16];
    float* out = (float*)d_out;

    cudaFuncSetAttribute(k_edge, cudaFuncAttributeMaxDynamicSharedMemorySize, K1_TOT * 4);
    cudaFuncSetAttribute(k_node, cudaFuncAttributeMaxDynamicSharedMemorySize, N_TOT * 4);

    k_edge<<<NB1, 192, K1_TOT * 4>>>(x, out, eW1, eb1, eW2, eb2, eW3, eb3);
    k_fin_edge<<<96, 256>>>(eg, ebt);
    k_node<<<NB2, 256, N_TOT * 4>>>(out, nW1, nb1, nW2, nb2, nW3, nb3);
    k_fin_node<<<32, 256>>>(ng, nbt);
    k_final<<<ROWS_C * 4 / 256, 256>>>(out);
}